// round 12
// baseline (speedup 1.0000x reference)
#include <cuda_runtime.h>
#include <cuda_bf16.h>
#include <math.h>
#include <cstdint>

#define BB   4
#define CH   128
#define HH   240
#define WW   320
#define NK   4000
#define NPOS 8
#define KSZ  3
#define HWSZ (HH*WW)
#define MAXOFF 80.0f

#define NKP_TOT (BB*NK)          // 16000
#define MROWS   (NKP_TOT*NPOS)   // 128000

// ---------------- scratch (static device globals; no runtime alloc) ------------
__device__ __align__(16) float g_xT[(size_t)BB*HWSZ*CH];        // NHWC
__device__ __align__(16) float2 g_pos[(size_t)MROWS];           // sample positions (px,py)
__device__ __align__(256) __nv_bfloat16 g_sfw_hi[CH*CH];        // [d][c]
__device__ __align__(256) __nv_bfloat16 g_sfw_lo[CH*CH];
__device__ __align__(256) __nv_bfloat16 g_agg_hi[NPOS*CH*CH];   // [p][d][c]
__device__ __align__(256) __nv_bfloat16 g_agg_lo[NPOS*CH*CH];

// ================= warp-MMA helpers (HMMA path, works on plain sm_103) ==========
__device__ __forceinline__ uint32_t smem_u32(const void* p) {
    return (uint32_t)__cvta_generic_to_shared(p);
}
__device__ __forceinline__ void ldsm4(uint32_t r[4], uint32_t addr) {
    asm volatile("ldmatrix.sync.aligned.m8n8.x4.shared.b16 {%0,%1,%2,%3}, [%4];"
                 : "=r"(r[0]), "=r"(r[1]), "=r"(r[2]), "=r"(r[3]) : "r"(addr));
}
__device__ __forceinline__ void mma16816(float d[4], const uint32_t a[4], const uint32_t b[2]) {
    asm volatile("mma.sync.aligned.m16n8k16.row.col.f32.bf16.bf16.f32 "
                 "{%0,%1,%2,%3}, {%4,%5,%6,%7}, {%8,%9}, {%0,%1,%2,%3};"
                 : "+f"(d[0]), "+f"(d[1]), "+f"(d[2]), "+f"(d[3])
                 : "r"(a[0]), "r"(a[1]), "r"(a[2]), "r"(a[3]), "r"(b[0]), "r"(b[1]));
}
__device__ __forceinline__ uint32_t pack2bf(float a, float b) {
    __nv_bfloat162 t = __floats2bfloat162_rn(a, b);
    return *(uint32_t*)&t;
}
// 16B-chunk XOR swizzle for a tile with 256B rows (16 chunks/row)
#define SW_OFF(row, chunk) ((uint32_t)(row) * 256u + ((uint32_t)((chunk) ^ ((row) & 7)) << 4))

#define CP_ASYNC16(dst, src) \
    asm volatile("cp.async.cg.shared.global [%0], [%1], 16;" :: "r"(dst), "l"(src))
#define CP_COMMIT() asm volatile("cp.async.commit_group;" ::: "memory")
#define CP_WAIT(n)  asm volatile("cp.async.wait_group %0;" :: "n"(n) : "memory")

// ---------------- K1: NCHW -> NHWC transpose ------------------------------------
__global__ void k_transpose(const float* __restrict__ x) {
    __shared__ float tile[32][33];
    int b  = blockIdx.z;
    int c0 = blockIdx.y * 32;
    int hw0 = blockIdx.x * 32;
    int tx = threadIdx.x, ty = threadIdx.y;     // 32 x 8
    const float* xb = x + (size_t)b * CH * HWSZ;
    #pragma unroll
    for (int i = ty; i < 32; i += 8)
        tile[i][tx] = xb[(size_t)(c0 + i) * HWSZ + hw0 + tx];
    __syncthreads();
    float* ob = g_xT + (size_t)b * HWSZ * CH;
    #pragma unroll
    for (int i = ty; i < 32; i += 8)
        ob[(size_t)(hw0 + i) * CH + c0 + tx] = tile[tx][i];
}

// ---------------- prep: split sf_w into bf16 hi/lo ([d][c] as-is) ---------------
__global__ void k_prep_sfw(const float* __restrict__ sfw) {
    int i = blockIdx.x * 256 + threadIdx.x;     // 16384 elems
    float v = sfw[i];
    __nv_bfloat16 h = __float2bfloat16(v);
    g_sfw_hi[i] = h;
    g_sfw_lo[i] = __float2bfloat16(v - __bfloat162float(h));
}

// ---------------- prep: agg [p][c][d] -> [p][d][c] bf16 hi/lo -------------------
__global__ void k_prep_agg(const float* __restrict__ agg) {
    __shared__ float t[32][33];
    int p  = blockIdx.z;
    int c0 = blockIdx.x * 32;
    int d0 = blockIdx.y * 32;
    int tx = threadIdx.x, ty = threadIdx.y;     // 32 x 8
    const float* src = agg + (size_t)p * CH * CH;
    #pragma unroll
    for (int i = ty; i < 32; i += 8)
        t[i][tx] = src[(size_t)(c0 + i) * CH + d0 + tx];
    __syncthreads();
    #pragma unroll
    for (int i = ty; i < 32; i += 8) {
        float v = t[tx][i];
        __nv_bfloat16 h = __float2bfloat16(v);
        size_t oi = (size_t)p * CH * CH + (size_t)(d0 + i) * CH + c0 + tx;
        g_agg_hi[oi] = h;
        g_agg_lo[oi] = __float2bfloat16(v - __bfloat162float(h));
    }
}

// ---------------- K2a: 2-keypoints-per-warp offset MLP -> sample positions ------
__global__ __launch_bounds__(256) void k_off(
        const float* __restrict__ kpts,
        const float* __restrict__ w1, const float* __restrict__ b1,
        const float* __restrict__ w2, const float* __restrict__ b2) {
    extern __shared__ float w1s[];            // [16][9][128]
    __shared__ float b1s[16];

    int tid = threadIdx.x;
    for (int idx = tid; idx < 16 * 9 * CH; idx += 256) {
        int k  = idx / (9 * CH);
        int r  = idx - k * 9 * CH;
        int ij = r >> 7;
        int c  = r & 127;
        w1s[idx] = w1[(k * CH + c) * 9 + ij];
    }
    if (tid < 16) b1s[tid] = b1[tid];
    __syncthreads();

    int warp = tid >> 5, lane = tid & 31;
    int kpa = blockIdx.x * 16 + warp * 2;
    int kpb = kpa + 1;

    float kxa = kpts[(size_t)kpa * 2 + 0], kya = kpts[(size_t)kpa * 2 + 1];
    float kxb = kpts[(size_t)kpb * 2 + 0], kyb = kpts[(size_t)kpb * 2 + 1];
    float kwxa = (kxa * 0.5f + 0.5f) * (float)(WW - 1);
    float kwya = (kya * 0.5f + 0.5f) * (float)(HH - 1);
    float kwxb = (kxb * 0.5f + 0.5f) * (float)(WW - 1);
    float kwyb = (kyb * 0.5f + 0.5f) * (float)(HH - 1);
    int cxa = min(max((int)((float)((int)kwxa) - 0.5f), 0), WW - 1 - KSZ);
    int cya = min(max((int)((float)((int)kwya) - 0.5f), 0), HH - 1 - KSZ);
    int cxb = min(max((int)((float)((int)kwxb) - 0.5f), 0), WW - 1 - KSZ);
    int cyb = min(max((int)((float)((int)kwyb) - 0.5f), 0), HH - 1 - KSZ);

    const float* basea = g_xT + (size_t)(kpa / NK) * HWSZ * CH + lane * 4;
    const float* baseb = g_xT + (size_t)(kpb / NK) * HWSZ * CH + lane * 4;

    float4 pa[9], pb[9];
    #pragma unroll
    for (int iy = 0; iy < 3; iy++)
        #pragma unroll
        for (int ix = 0; ix < 3; ix++) {
            pa[iy * 3 + ix] = *(const float4*)(basea + ((size_t)(cya + iy) * WW + (cxa + ix)) * CH);
            pb[iy * 3 + ix] = *(const float4*)(baseb + ((size_t)(cyb + iy) * WW + (cxb + ix)) * CH);
        }

    float acc_a[16], acc_b[16];
    #pragma unroll
    for (int k = 0; k < 16; k++) {
        float a = 0.f, b = 0.f;
        #pragma unroll
        for (int ij = 0; ij < 9; ij++) {
            float4 w = *(const float4*)&w1s[(k * 9 + ij) * CH + lane * 4];
            a = fmaf(pa[ij].x, w.x, a); a = fmaf(pa[ij].y, w.y, a);
            a = fmaf(pa[ij].z, w.z, a); a = fmaf(pa[ij].w, w.w, a);
            b = fmaf(pb[ij].x, w.x, b); b = fmaf(pb[ij].y, w.y, b);
            b = fmaf(pb[ij].z, w.z, b); b = fmaf(pb[ij].w, w.w, b);
        }
        acc_a[k] = a; acc_b[k] = b;
    }
    #pragma unroll
    for (int k = 0; k < 16; k++) {
        #pragma unroll
        for (int off = 16; off; off >>= 1) {
            acc_a[k] += __shfl_xor_sync(0xffffffffu, acc_a[k], off);
            acc_b[k] += __shfl_xor_sync(0xffffffffu, acc_b[k], off);
        }
    }

    int n = lane & 15;
    bool isB = lane >= 16;
    float s = b2[n];
    #pragma unroll
    for (int k = 0; k < 16; k++) {
        float v = (isB ? acc_b[k] : acc_a[k]) + b1s[k];
        s = fmaf(fmaxf(v, 0.f), w2[n * 16 + k], s);
    }
    s = fminf(fmaxf(s, -MAXOFF), MAXOFF);

    float oy = __shfl_sync(0xffffffffu, s, (lane & 7) + 8 + (lane & 16));
    if ((lane & 15) < 8) {
        int kp   = isB ? kpb : kpa;
        float kwx = isB ? kwxb : kwxa;
        float kwy = isB ? kwyb : kwya;
        g_pos[(size_t)kp * NPOS + (lane & 7)] = make_float2(kwx + s, kwy + oy);
    }
}

// ---------------- fused: bilinear gather + selu(feats@sfwT) @ agg + L2 norm -----
// F tile rows are WARP-PRIVATE: warp w gathers and ldsm's only rows 16w..16w+15,
// so the gather->MMA1 hazard needs only __syncwarp. B prefetched via cp.async.
#define OF_SF_HI  0
#define OF_SF_LO  (32*1024)
#define OF_F_HI   (64*1024)
#define OF_F_LO   (96*1024)
#define OF_B_HI   (128*1024)
#define OF_B_LO   (160*1024)
#define SMEM_FUSED (192*1024)

__device__ __forceinline__ void stage_tile(char* dst, const __nv_bfloat16* src,
                                           int row_stride, int tid) {
    for (int it = tid; it < 2048; it += 256) {
        int row = it >> 4, ch = it & 15;
        *(uint4*)(dst + SW_OFF(row, ch)) =
            *(const uint4*)(src + (size_t)row * row_stride + ch * 8);
    }
}
__device__ __forceinline__ void stage_async(uint32_t dst_sb, const __nv_bfloat16* src,
                                            int row_stride, int tid) {
    #pragma unroll
    for (int it = tid; it < 2048; it += 256) {
        int row = it >> 4, ch = it & 15;
        CP_ASYNC16(dst_sb + SW_OFF(row, ch),
                   (const void*)(src + (size_t)row * row_stride + ch * 8));
    }
}

// warp gathers its 16 keypoint rows for position g: bilinear + hi/lo split -> F tile
__device__ __forceinline__ void gather_F(char* smem, int kp0, int g, int m0w, int lane) {
    int rlane = lane >> 3;          // 0..3: row within quad
    int cg    = lane & 7;           // channel group of 16
    #pragma unroll
    for (int sub = 0; sub < 4; sub++) {
        int row = m0w + sub * 4 + rlane;
        int kp  = kp0 + row;
        float2 pos = g_pos[(size_t)kp * NPOS + g];
        float px = pos.x, py = pos.y;
        float x0f = floorf(px), y0f = floorf(py);
        float wx = px - x0f, wy = py - y0f;
        int ix0 = (int)x0f, iy0 = (int)y0f;
        bool xin0 = (x0f >= 0.f) & (x0f <= (float)(WW - 1));
        bool xin1 = (x0f + 1.f >= 0.f) & (x0f + 1.f <= (float)(WW - 1));
        bool yin0 = (y0f >= 0.f) & (y0f <= (float)(HH - 1));
        bool yin1 = (y0f + 1.f >= 0.f) & (y0f + 1.f <= (float)(HH - 1));
        int cx0 = min(max(ix0, 0), WW - 1), cx1 = min(max(ix0 + 1, 0), WW - 1);
        int cy0 = min(max(iy0, 0), HH - 1), cy1 = min(max(iy0 + 1, 0), HH - 1);

        const float* base = g_xT + (size_t)(kp / NK) * HWSZ * CH + cg * 16;
        const float* p00 = base + ((size_t)cy0 * WW + cx0) * CH;
        const float* p10 = base + ((size_t)cy0 * WW + cx1) * CH;
        const float* p01 = base + ((size_t)cy1 * WW + cx0) * CH;
        const float* p11 = base + ((size_t)cy1 * WW + cx1) * CH;

        float4 v00[4], v10[4], v01[4], v11[4];
        #pragma unroll
        for (int q = 0; q < 4; q++) {
            v00[q] = make_float4(0, 0, 0, 0);
            v10[q] = v00[q]; v01[q] = v00[q]; v11[q] = v00[q];
        }
        if (xin0 & yin0) {
            #pragma unroll
            for (int q = 0; q < 4; q++) v00[q] = *(const float4*)(p00 + q * 4);
        }
        if (xin1 & yin0) {
            #pragma unroll
            for (int q = 0; q < 4; q++) v10[q] = *(const float4*)(p10 + q * 4);
        }
        if (xin0 & yin1) {
            #pragma unroll
            for (int q = 0; q < 4; q++) v01[q] = *(const float4*)(p01 + q * 4);
        }
        if (xin1 & yin1) {
            #pragma unroll
            for (int q = 0; q < 4; q++) v11[q] = *(const float4*)(p11 + q * 4);
        }

        float w00 = (1.f - wx) * (1.f - wy), w10 = wx * (1.f - wy);
        float w01 = (1.f - wx) * wy,         w11 = wx * wy;
        uint32_t hi[8], lo[8];
        #pragma unroll
        for (int q = 0; q < 4; q++) {
            float f0 = v00[q].x * w00 + v10[q].x * w10 + v01[q].x * w01 + v11[q].x * w11;
            float f1 = v00[q].y * w00 + v10[q].y * w10 + v01[q].y * w01 + v11[q].y * w11;
            float f2 = v00[q].z * w00 + v10[q].z * w10 + v01[q].z * w01 + v11[q].z * w11;
            float f3 = v00[q].w * w00 + v10[q].w * w10 + v01[q].w * w01 + v11[q].w * w11;
            float h0 = __bfloat162float(__float2bfloat16(f0));
            float h1 = __bfloat162float(__float2bfloat16(f1));
            float h2 = __bfloat162float(__float2bfloat16(f2));
            float h3 = __bfloat162float(__float2bfloat16(f3));
            hi[q * 2 + 0] = pack2bf(f0, f1);
            hi[q * 2 + 1] = pack2bf(f2, f3);
            lo[q * 2 + 0] = pack2bf(f0 - h0, f1 - h1);
            lo[q * 2 + 1] = pack2bf(f2 - h2, f3 - h3);
        }
        uint32_t c0 = (uint32_t)cg * 2;
        *(uint4*)(smem + OF_F_HI + SW_OFF(row, c0))     = make_uint4(hi[0], hi[1], hi[2], hi[3]);
        *(uint4*)(smem + OF_F_HI + SW_OFF(row, c0 + 1)) = make_uint4(hi[4], hi[5], hi[6], hi[7]);
        *(uint4*)(smem + OF_F_LO + SW_OFF(row, c0))     = make_uint4(lo[0], lo[1], lo[2], lo[3]);
        *(uint4*)(smem + OF_F_LO + SW_OFF(row, c0 + 1)) = make_uint4(lo[4], lo[5], lo[6], lo[7]);
    }
}

__global__ __launch_bounds__(256) void k_fused(float* __restrict__ out) {
    extern __shared__ __align__(16) char smem[];
    int tid = threadIdx.x;
    int wid = tid >> 5, lane = tid & 31;
    int kp0 = blockIdx.x * 128;
    int m0w = wid * 16;

    uint32_t sb = smem_u32(smem);

    // prologue: SF plain; F_0 gathered; B_0 via cp.async
    stage_tile(smem + OF_SF_HI, g_sfw_hi, 128, tid);
    stage_tile(smem + OF_SF_LO, g_sfw_lo, 128, tid);
    gather_F(smem, kp0, 0, m0w, lane);
    stage_async(sb + OF_B_HI, g_agg_hi, 128, tid);
    stage_async(sb + OF_B_LO, g_agg_lo, 128, tid);
    CP_COMMIT();
    __syncthreads();   // SF visible to all warps (F is warp-private)

    int a_row = m0w + (lane & 15);
    int a_chA = (lane >> 4);
    int b_rowi = (lane & 7) + ((lane >> 4) << 3);
    int b_chA = (lane >> 3) & 1;

    float d2[16][4];
    #pragma unroll
    for (int n = 0; n < 16; n++)
        #pragma unroll
        for (int j = 0; j < 4; j++) d2[n][j] = 0.f;

    for (int g = 0; g < NPOS; g++) {
        __syncwarp();  // this warp's F_g STS visible to its own ldsm lanes

        // ---- MMA1: D1 = feats_g @ sfw^T (3-term split) ----
        float d1[16][4];
        #pragma unroll
        for (int n = 0; n < 16; n++)
            #pragma unroll
            for (int j = 0; j < 4; j++) d1[n][j] = 0.f;

        #pragma unroll
        for (int kt = 0; kt < 8; kt++) {
            uint32_t ah[4], al[4];
            ldsm4(ah, sb + OF_F_HI + SW_OFF(a_row, 2 * kt + a_chA));
            ldsm4(al, sb + OF_F_LO + SW_OFF(a_row, 2 * kt + a_chA));
            #pragma unroll
            for (int ntp = 0; ntp < 8; ntp++) {
                uint32_t bh[4], bl[4];
                ldsm4(bh, sb + OF_SF_HI + SW_OFF(16 * ntp + b_rowi, 2 * kt + b_chA));
                ldsm4(bl, sb + OF_SF_LO + SW_OFF(16 * ntp + b_rowi, 2 * kt + b_chA));
                mma16816(d1[2 * ntp],     ah, bh);
                mma16816(d1[2 * ntp],     ah, bl);
                mma16816(d1[2 * ntp],     al, bh);
                mma16816(d1[2 * ntp + 1], ah, bh + 2);
                mma16816(d1[2 * ntp + 1], ah, bl + 2);
                mma16816(d1[2 * ntp + 1], al, bh + 2);
            }
        }
        __syncwarp();  // warp done reading its F_g rows -> safe to overwrite

        // ---- gather F_{g+1} (warp-private rows; LDG latency overlaps SELU/MMA2) ----
        if (g + 1 < NPOS)
            gather_F(smem, kp0, g + 1, m0w, lane);

        // ---- SELU + re-fragment (regs only) ----
        const float SC = 1.0507009873554805f, AL = 1.6732632423543772f;
        uint32_t a2h[8][4], a2l[8][4];
        #pragma unroll
        for (int kt2 = 0; kt2 < 8; kt2++) {
            float z[8];
            #pragma unroll
            for (int j = 0; j < 4; j++) {
                float v0 = d1[2 * kt2][j];
                float v1 = d1[2 * kt2 + 1][j];
                z[j]     = (v0 > 0.f) ? SC * v0 : SC * AL * expm1f(v0);
                z[4 + j] = (v1 > 0.f) ? SC * v1 : SC * AL * expm1f(v1);
            }
            float h0 = __bfloat162float(__float2bfloat16(z[0]));
            float h1 = __bfloat162float(__float2bfloat16(z[1]));
            float h2 = __bfloat162float(__float2bfloat16(z[2]));
            float h3 = __bfloat162float(__float2bfloat16(z[3]));
            float h4 = __bfloat162float(__float2bfloat16(z[4]));
            float h5 = __bfloat162float(__float2bfloat16(z[5]));
            float h6 = __bfloat162float(__float2bfloat16(z[6]));
            float h7 = __bfloat162float(__float2bfloat16(z[7]));
            a2h[kt2][0] = pack2bf(z[0], z[1]);
            a2h[kt2][1] = pack2bf(z[2], z[3]);
            a2h[kt2][2] = pack2bf(z[4], z[5]);
            a2h[kt2][3] = pack2bf(z[6], z[7]);
            a2l[kt2][0] = pack2bf(z[0] - h0, z[1] - h1);
            a2l[kt2][1] = pack2bf(z[2] - h2, z[3] - h3);
            a2l[kt2][2] = pack2bf(z[4] - h4, z[5] - h5);
            a2l[kt2][3] = pack2bf(z[6] - h6, z[7] - h7);
        }

        // ---- B_g ready? (only B uses cp.async now) ----
        CP_WAIT(0);
        __syncthreads();

        // ---- MMA2: D2 += G_g @ agg_g^T (3-term split, acc over g) ----
        #pragma unroll
        for (int kt = 0; kt < 8; kt++) {
            #pragma unroll
            for (int ntp = 0; ntp < 8; ntp++) {
                uint32_t bh[4], bl[4];
                ldsm4(bh, sb + OF_B_HI + SW_OFF(16 * ntp + b_rowi, 2 * kt + b_chA));
                ldsm4(bl, sb + OF_B_LO + SW_OFF(16 * ntp + b_rowi, 2 * kt + b_chA));
                mma16816(d2[2 * ntp],     a2h[kt], bh);
                mma16816(d2[2 * ntp],     a2h[kt], bl);
                mma16816(d2[2 * ntp],     a2l[kt], bh);
                mma16816(d2[2 * ntp + 1], a2h[kt], bh + 2);
                mma16816(d2[2 * ntp + 1], a2h[kt], bl + 2);
                mma16816(d2[2 * ntp + 1], a2l[kt], bh + 2);
            }
        }
        __syncthreads();   // all warps done reading B_g -> buffer reusable

        // prefetch B_{g+1} (overlaps MMA1 of g+1)
        if (g + 1 < NPOS) {
            stage_async(sb + OF_B_HI, g_agg_hi + (size_t)(g + 1) * CH * CH, 128, tid);
            stage_async(sb + OF_B_LO, g_agg_lo + (size_t)(g + 1) * CH * CH, 128, tid);
            CP_COMMIT();
        }
    }

    // ---- epilogue: row L2 norm + store ----
    float ssA = 0.f, ssB = 0.f;
    #pragma unroll
    for (int n = 0; n < 16; n++) {
        ssA = fmaf(d2[n][0], d2[n][0], fmaf(d2[n][1], d2[n][1], ssA));
        ssB = fmaf(d2[n][2], d2[n][2], fmaf(d2[n][3], d2[n][3], ssB));
    }
    ssA += __shfl_xor_sync(0xffffffffu, ssA, 1);
    ssA += __shfl_xor_sync(0xffffffffu, ssA, 2);
    ssB += __shfl_xor_sync(0xffffffffu, ssB, 1);
    ssB += __shfl_xor_sync(0xffffffffu, ssB, 2);
    float invA = 1.f / fmaxf(sqrtf(ssA), 1e-12f);
    float invB = 1.f / fmaxf(sqrtf(ssB), 1e-12f);

    int gg = lane >> 2, t = lane & 3;
    float* rowA = out + (size_t)(kp0 + m0w + gg) * CH;
    float* rowB = out + (size_t)(kp0 + m0w + gg + 8) * CH;
    #pragma unroll
    for (int n = 0; n < 16; n++) {
        int col = n * 8 + 2 * t;
        *(float2*)(rowA + col) = make_float2(d2[n][0] * invA, d2[n][1] * invA);
        *(float2*)(rowB + col) = make_float2(d2[n][2] * invB, d2[n][3] * invB);
    }
}

// ---------------- launch ---------------------------------------------------------
extern "C" void kernel_launch(void* const* d_in, const int* in_sizes, int n_in,
                              void* d_out, int out_size) {
    (void)in_sizes; (void)n_in; (void)out_size;
    const float* x    = (const float*)d_in[0];
    const float* kpts = (const float*)d_in[1];
    const float* w1   = (const float*)d_in[2];
    const float* b1   = (const float*)d_in[3];
    const float* w2   = (const float*)d_in[4];
    const float* b2   = (const float*)d_in[5];
    const float* sfw  = (const float*)d_in[6];
    const float* aggw = (const float*)d_in[7];
    float* out = (float*)d_out;

    const int smemOff = 16 * 9 * CH * sizeof(float);   // 73.7 KB
    cudaFuncSetAttribute(k_off,   cudaFuncAttributeMaxDynamicSharedMemorySize, smemOff);
    cudaFuncSetAttribute(k_fused, cudaFuncAttributeMaxDynamicSharedMemorySize, SMEM_FUSED);

    k_transpose<<<dim3(HWSZ / 32, CH / 32, BB), dim3(32, 8)>>>(x);
    k_prep_sfw<<<64, 256>>>(sfw);
    k_prep_agg<<<dim3(4, 4, NPOS), dim3(32, 8)>>>(aggw);
    k_off<<<NKP_TOT / 16, 256, smemOff>>>(kpts, w1, b1, w2, b2);
    k_fused<<<NKP_TOT / 128, 256, SMEM_FUSED>>>(out);
}

// round 13
// speedup vs baseline: 1.0432x; 1.0432x over previous
#include <cuda_runtime.h>
#include <cuda_bf16.h>
#include <math.h>
#include <cstdint>

#define BB   4
#define CH   128
#define HH   240
#define WW   320
#define NK   4000
#define NPOS 8
#define KSZ  3
#define HWSZ (HH*WW)
#define MAXOFF 80.0f

#define NKP_TOT (BB*NK)          // 16000
#define MROWS   (NKP_TOT*NPOS)   // 128000

// ---------------- scratch (static device globals; no runtime alloc) ------------
__device__ __align__(16) float g_xT[(size_t)BB*HWSZ*CH];        // NHWC
__device__ __align__(16) float2 g_pos[(size_t)MROWS];           // sample positions (px,py)
__device__ __align__(256) __nv_bfloat16 g_fhi[(size_t)MROWS*CH];
__device__ __align__(256) __nv_bfloat16 g_flo[(size_t)MROWS*CH];
__device__ __align__(256) __nv_bfloat16 g_sfw_hi[CH*CH];        // [d][c]
__device__ __align__(256) __nv_bfloat16 g_sfw_lo[CH*CH];
__device__ __align__(256) __nv_bfloat16 g_agg_hi[NPOS*CH*CH];   // [p][d][c]
__device__ __align__(256) __nv_bfloat16 g_agg_lo[NPOS*CH*CH];

// ================= warp-MMA helpers (HMMA path, works on plain sm_103) ==========
__device__ __forceinline__ uint32_t smem_u32(const void* p) {
    return (uint32_t)__cvta_generic_to_shared(p);
}
__device__ __forceinline__ void ldsm4(uint32_t r[4], uint32_t addr) {
    asm volatile("ldmatrix.sync.aligned.m8n8.x4.shared.b16 {%0,%1,%2,%3}, [%4];"
                 : "=r"(r[0]), "=r"(r[1]), "=r"(r[2]), "=r"(r[3]) : "r"(addr));
}
__device__ __forceinline__ void mma16816(float d[4], const uint32_t a[4], const uint32_t b[2]) {
    asm volatile("mma.sync.aligned.m16n8k16.row.col.f32.bf16.bf16.f32 "
                 "{%0,%1,%2,%3}, {%4,%5,%6,%7}, {%8,%9}, {%0,%1,%2,%3};"
                 : "+f"(d[0]), "+f"(d[1]), "+f"(d[2]), "+f"(d[3])
                 : "r"(a[0]), "r"(a[1]), "r"(a[2]), "r"(a[3]), "r"(b[0]), "r"(b[1]));
}
__device__ __forceinline__ uint32_t pack2bf(float a, float b) {
    __nv_bfloat162 t = __floats2bfloat162_rn(a, b);
    return *(uint32_t*)&t;
}
// 16B-chunk XOR swizzle for a tile with 256B rows (16 chunks/row)
#define SW_OFF(row, chunk) ((uint32_t)(row) * 256u + ((uint32_t)((chunk) ^ ((row) & 7)) << 4))

#define CP_ASYNC16(dst, src) \
    asm volatile("cp.async.cg.shared.global [%0], [%1], 16;" :: "r"(dst), "l"(src))
#define CP_COMMIT() asm volatile("cp.async.commit_group;" ::: "memory")
#define CP_WAIT(n)  asm volatile("cp.async.wait_group %0;" :: "n"(n) : "memory")

// ---------------- K1: NCHW -> NHWC transpose ------------------------------------
__global__ void k_transpose(const float* __restrict__ x) {
    __shared__ float tile[32][33];
    int b  = blockIdx.z;
    int c0 = blockIdx.y * 32;
    int hw0 = blockIdx.x * 32;
    int tx = threadIdx.x, ty = threadIdx.y;     // 32 x 8
    const float* xb = x + (size_t)b * CH * HWSZ;
    #pragma unroll
    for (int i = ty; i < 32; i += 8)
        tile[i][tx] = xb[(size_t)(c0 + i) * HWSZ + hw0 + tx];
    __syncthreads();
    float* ob = g_xT + (size_t)b * HWSZ * CH;
    #pragma unroll
    for (int i = ty; i < 32; i += 8)
        ob[(size_t)(hw0 + i) * CH + c0 + tx] = tile[tx][i];
}

// ---------------- merged prep: agg transpose-split (z<NPOS) + sfw split (z==NPOS)
__global__ void k_prep(const float* __restrict__ agg, const float* __restrict__ sfw) {
    __shared__ float t[32][33];
    int p  = blockIdx.z;
    int tx = threadIdx.x, ty = threadIdx.y;     // 32 x 8
    if (p == NPOS) {
        // sfw elementwise hi/lo split ([d][c] kept as-is)
        int c0 = blockIdx.x * 32;
        int d0 = blockIdx.y * 32;
        #pragma unroll
        for (int i = ty; i < 32; i += 8) {
            int idx = (d0 + i) * CH + c0 + tx;
            float v = sfw[idx];
            __nv_bfloat16 h = __float2bfloat16(v);
            g_sfw_hi[idx] = h;
            g_sfw_lo[idx] = __float2bfloat16(v - __bfloat162float(h));
        }
        return;
    }
    int c0 = blockIdx.x * 32;
    int d0 = blockIdx.y * 32;
    const float* src = agg + (size_t)p * CH * CH;
    #pragma unroll
    for (int i = ty; i < 32; i += 8)
        t[i][tx] = src[(size_t)(c0 + i) * CH + d0 + tx];
    __syncthreads();
    #pragma unroll
    for (int i = ty; i < 32; i += 8) {
        float v = t[tx][i];
        __nv_bfloat16 h = __float2bfloat16(v);
        size_t oi = (size_t)p * CH * CH + (size_t)(d0 + i) * CH + c0 + tx;
        g_agg_hi[oi] = h;
        g_agg_lo[oi] = __float2bfloat16(v - __bfloat162float(h));
    }
}

// ---------------- K2a: 2-kp-per-warp offset MLP, 512 thr = 32 kp/block ----------
// w1 staged once per block and shared by 32 keypoints (halves staging work).
__global__ __launch_bounds__(512) void k_off(
        const float* __restrict__ kpts,
        const float* __restrict__ w1, const float* __restrict__ b1,
        const float* __restrict__ w2, const float* __restrict__ b2) {
    extern __shared__ float w1s[];            // [16][9][128]
    __shared__ float b1s[16];

    int tid = threadIdx.x;
    for (int idx = tid; idx < 16 * 9 * CH; idx += 512) {
        int k  = idx / (9 * CH);
        int r  = idx - k * 9 * CH;
        int ij = r >> 7;
        int c  = r & 127;
        w1s[idx] = w1[(k * CH + c) * 9 + ij];
    }
    if (tid < 16) b1s[tid] = b1[tid];
    __syncthreads();

    int warp = tid >> 5, lane = tid & 31;
    int kpa = blockIdx.x * 32 + warp * 2;
    int kpb = kpa + 1;

    float kxa = kpts[(size_t)kpa * 2 + 0], kya = kpts[(size_t)kpa * 2 + 1];
    float kxb = kpts[(size_t)kpb * 2 + 0], kyb = kpts[(size_t)kpb * 2 + 1];
    float kwxa = (kxa * 0.5f + 0.5f) * (float)(WW - 1);
    float kwya = (kya * 0.5f + 0.5f) * (float)(HH - 1);
    float kwxb = (kxb * 0.5f + 0.5f) * (float)(WW - 1);
    float kwyb = (kyb * 0.5f + 0.5f) * (float)(HH - 1);
    int cxa = min(max((int)((float)((int)kwxa) - 0.5f), 0), WW - 1 - KSZ);
    int cya = min(max((int)((float)((int)kwya) - 0.5f), 0), HH - 1 - KSZ);
    int cxb = min(max((int)((float)((int)kwxb) - 0.5f), 0), WW - 1 - KSZ);
    int cyb = min(max((int)((float)((int)kwyb) - 0.5f), 0), HH - 1 - KSZ);

    const float* basea = g_xT + (size_t)(kpa / NK) * HWSZ * CH + lane * 4;
    const float* baseb = g_xT + (size_t)(kpb / NK) * HWSZ * CH + lane * 4;

    float4 pa[9], pb[9];
    #pragma unroll
    for (int iy = 0; iy < 3; iy++)
        #pragma unroll
        for (int ix = 0; ix < 3; ix++) {
            pa[iy * 3 + ix] = *(const float4*)(basea + ((size_t)(cya + iy) * WW + (cxa + ix)) * CH);
            pb[iy * 3 + ix] = *(const float4*)(baseb + ((size_t)(cyb + iy) * WW + (cxb + ix)) * CH);
        }

    float acc_a[16], acc_b[16];
    #pragma unroll
    for (int k = 0; k < 16; k++) {
        float a = 0.f, b = 0.f;
        #pragma unroll
        for (int ij = 0; ij < 9; ij++) {
            float4 w = *(const float4*)&w1s[(k * 9 + ij) * CH + lane * 4];
            a = fmaf(pa[ij].x, w.x, a); a = fmaf(pa[ij].y, w.y, a);
            a = fmaf(pa[ij].z, w.z, a); a = fmaf(pa[ij].w, w.w, a);
            b = fmaf(pb[ij].x, w.x, b); b = fmaf(pb[ij].y, w.y, b);
            b = fmaf(pb[ij].z, w.z, b); b = fmaf(pb[ij].w, w.w, b);
        }
        acc_a[k] = a; acc_b[k] = b;
    }
    #pragma unroll
    for (int k = 0; k < 16; k++) {
        #pragma unroll
        for (int off = 16; off; off >>= 1) {
            acc_a[k] += __shfl_xor_sync(0xffffffffu, acc_a[k], off);
            acc_b[k] += __shfl_xor_sync(0xffffffffu, acc_b[k], off);
        }
    }

    int n = lane & 15;
    bool isB = lane >= 16;
    float s = b2[n];
    #pragma unroll
    for (int k = 0; k < 16; k++) {
        float v = (isB ? acc_b[k] : acc_a[k]) + b1s[k];
        s = fmaf(fmaxf(v, 0.f), w2[n * 16 + k], s);
    }
    s = fminf(fmaxf(s, -MAXOFF), MAXOFF);

    float oy = __shfl_sync(0xffffffffu, s, (lane & 7) + 8 + (lane & 16));
    if ((lane & 15) < 8) {
        int kp   = isB ? kpb : kpa;
        float kwx = isB ? kwxb : kwxa;
        float kwy = isB ? kwyb : kwya;
        g_pos[(size_t)kp * NPOS + (lane & 7)] = make_float2(kwx + s, kwy + oy);
    }
}

// ---------------- K2b: warp-per-sample bilinear gather -> feats hi/lo -----------
__global__ __launch_bounds__(256) void k_bil() {
    int s = blockIdx.x * 8 + (threadIdx.x >> 5);
    int lane = threadIdx.x & 31;
    int kp = s >> 3;
    int b  = kp / NK;

    float2 pos = g_pos[s];
    float px = pos.x, py = pos.y;
    float x0f = floorf(px), y0f = floorf(py);
    float wx = px - x0f, wy = py - y0f;
    int ix0 = (int)x0f, iy0 = (int)y0f;
    bool xin0 = (x0f >= 0.f) & (x0f <= (float)(WW - 1));
    bool xin1 = (x0f + 1.f >= 0.f) & (x0f + 1.f <= (float)(WW - 1));
    bool yin0 = (y0f >= 0.f) & (y0f <= (float)(HH - 1));
    bool yin1 = (y0f + 1.f >= 0.f) & (y0f + 1.f <= (float)(HH - 1));
    int cx0 = min(max(ix0, 0), WW - 1),     cx1 = min(max(ix0 + 1, 0), WW - 1);
    int cy0 = min(max(iy0, 0), HH - 1),     cy1 = min(max(iy0 + 1, 0), HH - 1);

    const float* base = g_xT + (size_t)b * HWSZ * CH + lane * 4;
    float4 v00 = make_float4(0, 0, 0, 0), v10 = v00, v01 = v00, v11 = v00;
    if (xin0 & yin0) v00 = *(const float4*)(base + ((size_t)cy0 * WW + cx0) * CH);
    if (xin1 & yin0) v10 = *(const float4*)(base + ((size_t)cy0 * WW + cx1) * CH);
    if (xin0 & yin1) v01 = *(const float4*)(base + ((size_t)cy1 * WW + cx0) * CH);
    if (xin1 & yin1) v11 = *(const float4*)(base + ((size_t)cy1 * WW + cx1) * CH);

    float w00 = (1.f - wx) * (1.f - wy), w10 = wx * (1.f - wy);
    float w01 = (1.f - wx) * wy,         w11 = wx * wy;
    float f0 = v00.x * w00 + v10.x * w10 + v01.x * w01 + v11.x * w11;
    float f1 = v00.y * w00 + v10.y * w10 + v01.y * w01 + v11.y * w11;
    float f2 = v00.z * w00 + v10.z * w10 + v01.z * w01 + v11.z * w11;
    float f3 = v00.w * w00 + v10.w * w10 + v01.w * w01 + v11.w * w11;

    float h0 = __bfloat162float(__float2bfloat16(f0));
    float h1 = __bfloat162float(__float2bfloat16(f1));
    float h2 = __bfloat162float(__float2bfloat16(f2));
    float h3 = __bfloat162float(__float2bfloat16(f3));

    size_t o = (size_t)s * CH + lane * 4;
    *(uint2*)(g_fhi + o) = make_uint2(pack2bf(f0, f1), pack2bf(f2, f3));
    *(uint2*)(g_flo + o) = make_uint2(pack2bf(f0 - h0, f1 - h1), pack2bf(f2 - h2, f3 - h3));
}

// ---------------- fused HMMA GEMM: selu(feats@sfwT) @ agg + L2 norm -------------
// Pipelined with cp.async: F_{g+1} streams during SELU+MMA2(g); B_{g+1} during MMA1(g+1).
#define OF_SF_HI  0
#define OF_SF_LO  (32*1024)
#define OF_F_HI   (64*1024)
#define OF_F_LO   (96*1024)
#define OF_B_HI   (128*1024)
#define OF_B_LO   (160*1024)
#define SMEM_FUSED (192*1024)

__device__ __forceinline__ void stage_tile(char* dst, const __nv_bfloat16* src,
                                           int row_stride, int tid) {
    for (int it = tid; it < 2048; it += 256) {
        int row = it >> 4, ch = it & 15;
        *(uint4*)(dst + SW_OFF(row, ch)) =
            *(const uint4*)(src + (size_t)row * row_stride + ch * 8);
    }
}
__device__ __forceinline__ void stage_async(uint32_t dst_sb, const __nv_bfloat16* src,
                                            int row_stride, int tid) {
    #pragma unroll
    for (int it = tid; it < 2048; it += 256) {
        int row = it >> 4, ch = it & 15;
        CP_ASYNC16(dst_sb + SW_OFF(row, ch),
                   (const void*)(src + (size_t)row * row_stride + ch * 8));
    }
}

__global__ __launch_bounds__(256) void k_fused(float* __restrict__ out) {
    extern __shared__ __align__(16) char smem[];
    int tid = threadIdx.x;
    int wid = tid >> 5, lane = tid & 31;
    int kp0 = blockIdx.x * 128;
    int m0w = wid * 16;

    uint32_t sb = smem_u32(smem);

    // prologue: SF plain; F0 then B0 via cp.async (two groups)
    stage_tile(smem + OF_SF_HI, g_sfw_hi, 128, tid);
    stage_tile(smem + OF_SF_LO, g_sfw_lo, 128, tid);
    stage_async(sb + OF_F_HI, g_fhi + ((size_t)kp0 * NPOS + 0) * CH, NPOS * CH, tid);
    stage_async(sb + OF_F_LO, g_flo + ((size_t)kp0 * NPOS + 0) * CH, NPOS * CH, tid);
    CP_COMMIT();
    stage_async(sb + OF_B_HI, g_agg_hi, 128, tid);
    stage_async(sb + OF_B_LO, g_agg_lo, 128, tid);
    CP_COMMIT();

    int a_row = m0w + (lane & 15);
    int a_chA = (lane >> 4);
    int b_rowi = (lane & 7) + ((lane >> 4) << 3);
    int b_chA = (lane >> 3) & 1;

    float d2[16][4];
    #pragma unroll
    for (int n = 0; n < 16; n++)
        #pragma unroll
        for (int j = 0; j < 4; j++) d2[n][j] = 0.f;

    for (int g = 0; g < NPOS; g++) {
        // F_g must be complete (allow newest group — B_g — to stay in flight)
        CP_WAIT(1);
        __syncthreads();

        // ---- MMA1: D1 = feats_g @ sfw^T (3-term split) ----
        float d1[16][4];
        #pragma unroll
        for (int n = 0; n < 16; n++)
            #pragma unroll
            for (int j = 0; j < 4; j++) d1[n][j] = 0.f;

        #pragma unroll
        for (int kt = 0; kt < 8; kt++) {
            uint32_t ah[4], al[4];
            ldsm4(ah, sb + OF_F_HI + SW_OFF(a_row, 2 * kt + a_chA));
            ldsm4(al, sb + OF_F_LO + SW_OFF(a_row, 2 * kt + a_chA));
            #pragma unroll
            for (int ntp = 0; ntp < 8; ntp++) {
                uint32_t bh[4], bl[4];
                ldsm4(bh, sb + OF_SF_HI + SW_OFF(16 * ntp + b_rowi, 2 * kt + b_chA));
                ldsm4(bl, sb + OF_SF_LO + SW_OFF(16 * ntp + b_rowi, 2 * kt + b_chA));
                mma16816(d1[2 * ntp],     ah, bh);
                mma16816(d1[2 * ntp],     ah, bl);
                mma16816(d1[2 * ntp],     al, bh);
                mma16816(d1[2 * ntp + 1], ah, bh + 2);
                mma16816(d1[2 * ntp + 1], ah, bl + 2);
                mma16816(d1[2 * ntp + 1], al, bh + 2);
            }
        }
        __syncthreads();   // all warps done reading F_g -> buffer reusable

        // prefetch F_{g+1} (overlaps SELU + MMA2)
        if (g + 1 < NPOS) {
            stage_async(sb + OF_F_HI, g_fhi + ((size_t)kp0 * NPOS + g + 1) * CH, NPOS * CH, tid);
            stage_async(sb + OF_F_LO, g_flo + ((size_t)kp0 * NPOS + g + 1) * CH, NPOS * CH, tid);
        }
        CP_COMMIT();       // keep group parity fixed (empty group when g==7)

        // ---- SELU + re-fragment (regs only) ----
        const float SC = 1.0507009873554805f, AL = 1.6732632423543772f;
        uint32_t a2h[8][4], a2l[8][4];
        #pragma unroll
        for (int kt2 = 0; kt2 < 8; kt2++) {
            float z[8];
            #pragma unroll
            for (int j = 0; j < 4; j++) {
                float v0 = d1[2 * kt2][j];
                float v1 = d1[2 * kt2 + 1][j];
                z[j]     = (v0 > 0.f) ? SC * v0 : SC * AL * expm1f(v0);
                z[4 + j] = (v1 > 0.f) ? SC * v1 : SC * AL * expm1f(v1);
            }
            float h0 = __bfloat162float(__float2bfloat16(z[0]));
            float h1 = __bfloat162float(__float2bfloat16(z[1]));
            float h2 = __bfloat162float(__float2bfloat16(z[2]));
            float h3 = __bfloat162float(__float2bfloat16(z[3]));
            float h4 = __bfloat162float(__float2bfloat16(z[4]));
            float h5 = __bfloat162float(__float2bfloat16(z[5]));
            float h6 = __bfloat162float(__float2bfloat16(z[6]));
            float h7 = __bfloat162float(__float2bfloat16(z[7]));
            a2h[kt2][0] = pack2bf(z[0], z[1]);
            a2h[kt2][1] = pack2bf(z[2], z[3]);
            a2h[kt2][2] = pack2bf(z[4], z[5]);
            a2h[kt2][3] = pack2bf(z[6], z[7]);
            a2l[kt2][0] = pack2bf(z[0] - h0, z[1] - h1);
            a2l[kt2][1] = pack2bf(z[2] - h2, z[3] - h3);
            a2l[kt2][2] = pack2bf(z[4] - h4, z[5] - h5);
            a2l[kt2][3] = pack2bf(z[6] - h6, z[7] - h7);
        }

        // B_g must be complete (allow newest group — F_{g+1} — to stay in flight)
        if (g + 1 < NPOS) { CP_WAIT(1); } else { CP_WAIT(0); }
        __syncthreads();

        // ---- MMA2: D2 += G_g @ agg_g^T (3-term split, acc over g) ----
        #pragma unroll
        for (int kt = 0; kt < 8; kt++) {
            #pragma unroll
            for (int ntp = 0; ntp < 8; ntp++) {
                uint32_t bh[4], bl[4];
                ldsm4(bh, sb + OF_B_HI + SW_OFF(16 * ntp + b_rowi, 2 * kt + b_chA));
                ldsm4(bl, sb + OF_B_LO + SW_OFF(16 * ntp + b_rowi, 2 * kt + b_chA));
                mma16816(d2[2 * ntp],     a2h[kt], bh);
                mma16816(d2[2 * ntp],     a2h[kt], bl);
                mma16816(d2[2 * ntp],     a2l[kt], bh);
                mma16816(d2[2 * ntp + 1], a2h[kt], bh + 2);
                mma16816(d2[2 * ntp + 1], a2h[kt], bl + 2);
                mma16816(d2[2 * ntp + 1], a2l[kt], bh + 2);
            }
        }
        __syncthreads();   // all warps done reading B_g -> buffer reusable

        // prefetch B_{g+1} (overlaps MMA1 of g+1)
        if (g + 1 < NPOS) {
            stage_async(sb + OF_B_HI, g_agg_hi + (size_t)(g + 1) * CH * CH, 128, tid);
            stage_async(sb + OF_B_LO, g_agg_lo + (size_t)(g + 1) * CH * CH, 128, tid);
            CP_COMMIT();
        }
    }

    // ---- epilogue: row L2 norm + store ----
    float ssA = 0.f, ssB = 0.f;
    #pragma unroll
    for (int n = 0; n < 16; n++) {
        ssA = fmaf(d2[n][0], d2[n][0], fmaf(d2[n][1], d2[n][1], ssA));
        ssB = fmaf(d2[n][2], d2[n][2], fmaf(d2[n][3], d2[n][3], ssB));
    }
    ssA += __shfl_xor_sync(0xffffffffu, ssA, 1);
    ssA += __shfl_xor_sync(0xffffffffu, ssA, 2);
    ssB += __shfl_xor_sync(0xffffffffu, ssB, 1);
    ssB += __shfl_xor_sync(0xffffffffu, ssB, 2);
    float invA = 1.f / fmaxf(sqrtf(ssA), 1e-12f);
    float invB = 1.f / fmaxf(sqrtf(ssB), 1e-12f);

    int gg = lane >> 2, t = lane & 3;
    float* rowA = out + (size_t)(kp0 + m0w + gg) * CH;
    float* rowB = out + (size_t)(kp0 + m0w + gg + 8) * CH;
    #pragma unroll
    for (int n = 0; n < 16; n++) {
        int col = n * 8 + 2 * t;
        *(float2*)(rowA + col) = make_float2(d2[n][0] * invA, d2[n][1] * invA);
        *(float2*)(rowB + col) = make_float2(d2[n][2] * invB, d2[n][3] * invB);
    }
}

// ---------------- launch ---------------------------------------------------------
extern "C" void kernel_launch(void* const* d_in, const int* in_sizes, int n_in,
                              void* d_out, int out_size) {
    (void)in_sizes; (void)n_in; (void)out_size;
    const float* x    = (const float*)d_in[0];
    const float* kpts = (const float*)d_in[1];
    const float* w1   = (const float*)d_in[2];
    const float* b1   = (const float*)d_in[3];
    const float* w2   = (const float*)d_in[4];
    const float* b2   = (const float*)d_in[5];
    const float* sfw  = (const float*)d_in[6];
    const float* aggw = (const float*)d_in[7];
    float* out = (float*)d_out;

    const int smemOff = 16 * 9 * CH * sizeof(float);   // 73.7 KB
    cudaFuncSetAttribute(k_off,   cudaFuncAttributeMaxDynamicSharedMemorySize, smemOff);
    cudaFuncSetAttribute(k_fused, cudaFuncAttributeMaxDynamicSharedMemorySize, SMEM_FUSED);

    k_transpose<<<dim3(HWSZ / 32, CH / 32, BB), dim3(32, 8)>>>(x);
    k_prep<<<dim3(4, 4, NPOS + 1), dim3(32, 8)>>>(aggw, sfw);
    k_off<<<NKP_TOT / 32, 512, smemOff>>>(kpts, w1, b1, w2, b2);
    k_bil<<<MROWS / 8, 256>>>();
    k_fused<<<NKP_TOT / 128, 256, SMEM_FUSED>>>(out);
}

// round 14
// speedup vs baseline: 1.0893x; 1.0442x over previous
#include <cuda_runtime.h>
#include <cuda_bf16.h>
#include <math.h>
#include <cstdint>

#define BB   4
#define CH   128
#define HH   240
#define WW   320
#define NK   4000
#define NPOS 8
#define KSZ  3
#define HWSZ (HH*WW)
#define MAXOFF 80.0f

#define NKP_TOT (BB*NK)          // 16000
#define MROWS   (NKP_TOT*NPOS)   // 128000

// ---------------- scratch (static device globals; no runtime alloc) ------------
__device__ __align__(16) float g_xT[(size_t)BB*HWSZ*CH];        // NHWC
__device__ __align__(16) float2 g_pos[(size_t)MROWS];           // sample positions (px,py)
__device__ __align__(256) __nv_bfloat16 g_fhi[(size_t)MROWS*CH];
__device__ __align__(256) __nv_bfloat16 g_flo[(size_t)MROWS*CH];
__device__ __align__(256) __nv_bfloat16 g_sfw_hi[CH*CH];        // [d][c]
__device__ __align__(256) __nv_bfloat16 g_sfw_lo[CH*CH];
__device__ __align__(256) __nv_bfloat16 g_agg_hi[NPOS*CH*CH];   // [p][d][c]
__device__ __align__(256) __nv_bfloat16 g_agg_lo[NPOS*CH*CH];

// ================= warp-MMA helpers (HMMA path, works on plain sm_103) ==========
__device__ __forceinline__ uint32_t smem_u32(const void* p) {
    return (uint32_t)__cvta_generic_to_shared(p);
}
__device__ __forceinline__ void ldsm4(uint32_t r[4], uint32_t addr) {
    asm volatile("ldmatrix.sync.aligned.m8n8.x4.shared.b16 {%0,%1,%2,%3}, [%4];"
                 : "=r"(r[0]), "=r"(r[1]), "=r"(r[2]), "=r"(r[3]) : "r"(addr));
}
__device__ __forceinline__ void mma16816(float d[4], const uint32_t a[4], const uint32_t b[2]) {
    asm volatile("mma.sync.aligned.m16n8k16.row.col.f32.bf16.bf16.f32 "
                 "{%0,%1,%2,%3}, {%4,%5,%6,%7}, {%8,%9}, {%0,%1,%2,%3};"
                 : "+f"(d[0]), "+f"(d[1]), "+f"(d[2]), "+f"(d[3])
                 : "r"(a[0]), "r"(a[1]), "r"(a[2]), "r"(a[3]), "r"(b[0]), "r"(b[1]));
}
__device__ __forceinline__ uint32_t pack2bf(float a, float b) {
    __nv_bfloat162 t = __floats2bfloat162_rn(a, b);
    return *(uint32_t*)&t;
}
// 16B-chunk XOR swizzle for a tile with 256B rows (16 chunks/row)
#define SW_OFF(row, chunk) ((uint32_t)(row) * 256u + ((uint32_t)((chunk) ^ ((row) & 7)) << 4))

#define CP_ASYNC16(dst, src) \
    asm volatile("cp.async.cg.shared.global [%0], [%1], 16;" :: "r"(dst), "l"(src))
#define CP_COMMIT() asm volatile("cp.async.commit_group;" ::: "memory")
#define CP_WAIT(n)  asm volatile("cp.async.wait_group %0;" :: "n"(n) : "memory")

// ---------------- K1: NCHW -> NHWC transpose ------------------------------------
__global__ void k_transpose(const float* __restrict__ x) {
    __shared__ float tile[32][33];
    int b  = blockIdx.z;
    int c0 = blockIdx.y * 32;
    int hw0 = blockIdx.x * 32;
    int tx = threadIdx.x, ty = threadIdx.y;     // 32 x 8
    const float* xb = x + (size_t)b * CH * HWSZ;
    #pragma unroll
    for (int i = ty; i < 32; i += 8)
        tile[i][tx] = xb[(size_t)(c0 + i) * HWSZ + hw0 + tx];
    __syncthreads();
    float* ob = g_xT + (size_t)b * HWSZ * CH;
    #pragma unroll
    for (int i = ty; i < 32; i += 8)
        ob[(size_t)(hw0 + i) * CH + c0 + tx] = tile[tx][i];
}

// ---------------- merged prep: agg transpose-split (z<NPOS) + sfw split (z==NPOS)
__global__ void k_prep(const float* __restrict__ agg, const float* __restrict__ sfw) {
    __shared__ float t[32][33];
    int p  = blockIdx.z;
    int tx = threadIdx.x, ty = threadIdx.y;     // 32 x 8
    if (p == NPOS) {
        int c0 = blockIdx.x * 32;
        int d0 = blockIdx.y * 32;
        #pragma unroll
        for (int i = ty; i < 32; i += 8) {
            int idx = (d0 + i) * CH + c0 + tx;
            float v = sfw[idx];
            __nv_bfloat16 h = __float2bfloat16(v);
            g_sfw_hi[idx] = h;
            g_sfw_lo[idx] = __float2bfloat16(v - __bfloat162float(h));
        }
        return;
    }
    int c0 = blockIdx.x * 32;
    int d0 = blockIdx.y * 32;
    const float* src = agg + (size_t)p * CH * CH;
    #pragma unroll
    for (int i = ty; i < 32; i += 8)
        t[i][tx] = src[(size_t)(c0 + i) * CH + d0 + tx];
    __syncthreads();
    #pragma unroll
    for (int i = ty; i < 32; i += 8) {
        float v = t[tx][i];
        __nv_bfloat16 h = __float2bfloat16(v);
        size_t oi = (size_t)p * CH * CH + (size_t)(d0 + i) * CH + c0 + tx;
        g_agg_hi[oi] = h;
        g_agg_lo[oi] = __float2bfloat16(v - __bfloat162float(h));
    }
}

// ---------------- K2a: 2-kp-per-warp offset MLP, 512 thr = 32 kp/block ----------
__global__ __launch_bounds__(512) void k_off(
        const float* __restrict__ kpts,
        const float* __restrict__ w1, const float* __restrict__ b1,
        const float* __restrict__ w2, const float* __restrict__ b2) {
    extern __shared__ float w1s[];            // [16][9][128]
    __shared__ float b1s[16];

    int tid = threadIdx.x;
    for (int idx = tid; idx < 16 * 9 * CH; idx += 512) {
        int k  = idx / (9 * CH);
        int r  = idx - k * 9 * CH;
        int ij = r >> 7;
        int c  = r & 127;
        w1s[idx] = w1[(k * CH + c) * 9 + ij];
    }
    if (tid < 16) b1s[tid] = b1[tid];
    __syncthreads();

    int warp = tid >> 5, lane = tid & 31;
    int kpa = blockIdx.x * 32 + warp * 2;
    int kpb = kpa + 1;

    float kxa = kpts[(size_t)kpa * 2 + 0], kya = kpts[(size_t)kpa * 2 + 1];
    float kxb = kpts[(size_t)kpb * 2 + 0], kyb = kpts[(size_t)kpb * 2 + 1];
    float kwxa = (kxa * 0.5f + 0.5f) * (float)(WW - 1);
    float kwya = (kya * 0.5f + 0.5f) * (float)(HH - 1);
    float kwxb = (kxb * 0.5f + 0.5f) * (float)(WW - 1);
    float kwyb = (kyb * 0.5f + 0.5f) * (float)(HH - 1);
    int cxa = min(max((int)((float)((int)kwxa) - 0.5f), 0), WW - 1 - KSZ);
    int cya = min(max((int)((float)((int)kwya) - 0.5f), 0), HH - 1 - KSZ);
    int cxb = min(max((int)((float)((int)kwxb) - 0.5f), 0), WW - 1 - KSZ);
    int cyb = min(max((int)((float)((int)kwyb) - 0.5f), 0), HH - 1 - KSZ);

    const float* basea = g_xT + (size_t)(kpa / NK) * HWSZ * CH + lane * 4;
    const float* baseb = g_xT + (size_t)(kpb / NK) * HWSZ * CH + lane * 4;

    float4 pa[9], pb[9];
    #pragma unroll
    for (int iy = 0; iy < 3; iy++)
        #pragma unroll
        for (int ix = 0; ix < 3; ix++) {
            pa[iy * 3 + ix] = *(const float4*)(basea + ((size_t)(cya + iy) * WW + (cxa + ix)) * CH);
            pb[iy * 3 + ix] = *(const float4*)(baseb + ((size_t)(cyb + iy) * WW + (cxb + ix)) * CH);
        }

    float acc_a[16], acc_b[16];
    #pragma unroll
    for (int k = 0; k < 16; k++) {
        float a = 0.f, b = 0.f;
        #pragma unroll
        for (int ij = 0; ij < 9; ij++) {
            float4 w = *(const float4*)&w1s[(k * 9 + ij) * CH + lane * 4];
            a = fmaf(pa[ij].x, w.x, a); a = fmaf(pa[ij].y, w.y, a);
            a = fmaf(pa[ij].z, w.z, a); a = fmaf(pa[ij].w, w.w, a);
            b = fmaf(pb[ij].x, w.x, b); b = fmaf(pb[ij].y, w.y, b);
            b = fmaf(pb[ij].z, w.z, b); b = fmaf(pb[ij].w, w.w, b);
        }
        acc_a[k] = a; acc_b[k] = b;
    }
    #pragma unroll
    for (int k = 0; k < 16; k++) {
        #pragma unroll
        for (int off = 16; off; off >>= 1) {
            acc_a[k] += __shfl_xor_sync(0xffffffffu, acc_a[k], off);
            acc_b[k] += __shfl_xor_sync(0xffffffffu, acc_b[k], off);
        }
    }

    int n = lane & 15;
    bool isB = lane >= 16;
    float s = b2[n];
    #pragma unroll
    for (int k = 0; k < 16; k++) {
        float v = (isB ? acc_b[k] : acc_a[k]) + b1s[k];
        s = fmaf(fmaxf(v, 0.f), w2[n * 16 + k], s);
    }
    s = fminf(fmaxf(s, -MAXOFF), MAXOFF);

    float oy = __shfl_sync(0xffffffffu, s, (lane & 7) + 8 + (lane & 16));
    if ((lane & 15) < 8) {
        int kp   = isB ? kpb : kpa;
        float kwx = isB ? kwxb : kwxa;
        float kwy = isB ? kwyb : kwya;
        g_pos[(size_t)kp * NPOS + (lane & 7)] = make_float2(kwx + s, kwy + oy);
    }
}

// ---------------- K2b: warp-per-sample bilinear gather -> feats hi/lo -----------
__global__ __launch_bounds__(256) void k_bil() {
    int s = blockIdx.x * 8 + (threadIdx.x >> 5);
    int lane = threadIdx.x & 31;
    int kp = s >> 3;
    int b  = kp / NK;

    float2 pos = g_pos[s];
    float px = pos.x, py = pos.y;
    float x0f = floorf(px), y0f = floorf(py);
    float wx = px - x0f, wy = py - y0f;
    int ix0 = (int)x0f, iy0 = (int)y0f;
    bool xin0 = (x0f >= 0.f) & (x0f <= (float)(WW - 1));
    bool xin1 = (x0f + 1.f >= 0.f) & (x0f + 1.f <= (float)(WW - 1));
    bool yin0 = (y0f >= 0.f) & (y0f <= (float)(HH - 1));
    bool yin1 = (y0f + 1.f >= 0.f) & (y0f + 1.f <= (float)(HH - 1));
    int cx0 = min(max(ix0, 0), WW - 1),     cx1 = min(max(ix0 + 1, 0), WW - 1);
    int cy0 = min(max(iy0, 0), HH - 1),     cy1 = min(max(iy0 + 1, 0), HH - 1);

    const float* base = g_xT + (size_t)b * HWSZ * CH + lane * 4;
    float4 v00 = make_float4(0, 0, 0, 0), v10 = v00, v01 = v00, v11 = v00;
    if (xin0 & yin0) v00 = *(const float4*)(base + ((size_t)cy0 * WW + cx0) * CH);
    if (xin1 & yin0) v10 = *(const float4*)(base + ((size_t)cy0 * WW + cx1) * CH);
    if (xin0 & yin1) v01 = *(const float4*)(base + ((size_t)cy1 * WW + cx0) * CH);
    if (xin1 & yin1) v11 = *(const float4*)(base + ((size_t)cy1 * WW + cx1) * CH);

    float w00 = (1.f - wx) * (1.f - wy), w10 = wx * (1.f - wy);
    float w01 = (1.f - wx) * wy,         w11 = wx * wy;
    float f0 = v00.x * w00 + v10.x * w10 + v01.x * w01 + v11.x * w11;
    float f1 = v00.y * w00 + v10.y * w10 + v01.y * w01 + v11.y * w11;
    float f2 = v00.z * w00 + v10.z * w10 + v01.z * w01 + v11.z * w11;
    float f3 = v00.w * w00 + v10.w * w10 + v01.w * w01 + v11.w * w11;

    float h0 = __bfloat162float(__float2bfloat16(f0));
    float h1 = __bfloat162float(__float2bfloat16(f1));
    float h2 = __bfloat162float(__float2bfloat16(f2));
    float h3 = __bfloat162float(__float2bfloat16(f3));

    size_t o = (size_t)s * CH + lane * 4;
    *(uint2*)(g_fhi + o) = make_uint2(pack2bf(f0, f1), pack2bf(f2, f3));
    *(uint2*)(g_flo + o) = make_uint2(pack2bf(f0 - h0, f1 - h1), pack2bf(f2 - h2, f3 - h3));
}

// ---------------- fused HMMA GEMM: M=64 tiles, streamed B-slot, 2 blocks/SM -----
// SMEM: F (hi 16K + lo 16K) + B-slot (hi 32K + lo 32K) = 96KB -> 2 blocks/SM.
// B-slot alternates sfw (MMA1) and agg_g (MMA2) via cp.async.
#define OF3_F_HI  0
#define OF3_F_LO  (16*1024)
#define OF3_B_HI  (32*1024)
#define OF3_B_LO  (64*1024)
#define SMEM_FUSED (96*1024)

// stage a [rows x 128 bf16] tile (rows*16 chunks) with 128 threads
__device__ __forceinline__ void stage_async_n(uint32_t dst_sb, const __nv_bfloat16* src,
                                              int row_stride, int tid, int nchunk) {
    #pragma unroll 4
    for (int it = tid; it < nchunk; it += 128) {
        int row = it >> 4, ch = it & 15;
        CP_ASYNC16(dst_sb + SW_OFF(row, ch),
                   (const void*)(src + (size_t)row * row_stride + ch * 8));
    }
}

__global__ __launch_bounds__(128, 2) void k_fused(float* __restrict__ out) {
    extern __shared__ __align__(16) char smem[];
    int tid = threadIdx.x;
    int wid = tid >> 5, lane = tid & 31;
    int kp0 = blockIdx.x * 64;
    int m0w = wid * 16;

    uint32_t sb = smem_u32(smem);

    // prologue: F_0 (group), sfw -> B-slot (group)
    stage_async_n(sb + OF3_F_HI, g_fhi + ((size_t)kp0 * NPOS + 0) * CH, NPOS * CH, tid, 1024);
    stage_async_n(sb + OF3_F_LO, g_flo + ((size_t)kp0 * NPOS + 0) * CH, NPOS * CH, tid, 1024);
    CP_COMMIT();
    stage_async_n(sb + OF3_B_HI, g_sfw_hi, CH, tid, 2048);
    stage_async_n(sb + OF3_B_LO, g_sfw_lo, CH, tid, 2048);
    CP_COMMIT();

    int a_row = m0w + (lane & 15);
    int a_chA = (lane >> 4);
    int b_rowi = (lane & 7) + ((lane >> 4) << 3);
    int b_chA = (lane >> 3) & 1;

    float d2[16][4];
    #pragma unroll
    for (int n = 0; n < 16; n++)
        #pragma unroll
        for (int j = 0; j < 4; j++) d2[n][j] = 0.f;

    for (int g = 0; g < NPOS; g++) {
        // F_g + sfw must be in smem
        CP_WAIT(0);
        __syncthreads();

        // ---- MMA1: D1 = feats_g @ sfw^T (3-term split) ----
        float d1[16][4];
        #pragma unroll
        for (int n = 0; n < 16; n++)
            #pragma unroll
            for (int j = 0; j < 4; j++) d1[n][j] = 0.f;

        #pragma unroll
        for (int kt = 0; kt < 8; kt++) {
            uint32_t ah[4], al[4];
            ldsm4(ah, sb + OF3_F_HI + SW_OFF(a_row, 2 * kt + a_chA));
            ldsm4(al, sb + OF3_F_LO + SW_OFF(a_row, 2 * kt + a_chA));
            #pragma unroll
            for (int ntp = 0; ntp < 8; ntp++) {
                uint32_t bh[4], bl[4];
                ldsm4(bh, sb + OF3_B_HI + SW_OFF(16 * ntp + b_rowi, 2 * kt + b_chA));
                ldsm4(bl, sb + OF3_B_LO + SW_OFF(16 * ntp + b_rowi, 2 * kt + b_chA));
                mma16816(d1[2 * ntp],     ah, bh);
                mma16816(d1[2 * ntp],     ah, bl);
                mma16816(d1[2 * ntp],     al, bh);
                mma16816(d1[2 * ntp + 1], ah, bh + 2);
                mma16816(d1[2 * ntp + 1], ah, bl + 2);
                mma16816(d1[2 * ntp + 1], al, bh + 2);
            }
        }
        __syncthreads();   // all warps done reading F_g and B-slot(sfw)

        // stream agg_g into B-slot (group X), then F_{g+1} (group Y)
        stage_async_n(sb + OF3_B_HI, g_agg_hi + (size_t)g * CH * CH, CH, tid, 2048);
        stage_async_n(sb + OF3_B_LO, g_agg_lo + (size_t)g * CH * CH, CH, tid, 2048);
        CP_COMMIT();   // X
        if (g + 1 < NPOS) {
            stage_async_n(sb + OF3_F_HI, g_fhi + ((size_t)kp0 * NPOS + g + 1) * CH, NPOS * CH, tid, 1024);
            stage_async_n(sb + OF3_F_LO, g_flo + ((size_t)kp0 * NPOS + g + 1) * CH, NPOS * CH, tid, 1024);
        }
        CP_COMMIT();   // Y (possibly empty)

        // ---- SELU + re-fragment (regs only) ----
        const float SC = 1.0507009873554805f, AL = 1.6732632423543772f;
        uint32_t a2h[8][4], a2l[8][4];
        #pragma unroll
        for (int kt2 = 0; kt2 < 8; kt2++) {
            float z[8];
            #pragma unroll
            for (int j = 0; j < 4; j++) {
                float v0 = d1[2 * kt2][j];
                float v1 = d1[2 * kt2 + 1][j];
                z[j]     = (v0 > 0.f) ? SC * v0 : SC * AL * expm1f(v0);
                z[4 + j] = (v1 > 0.f) ? SC * v1 : SC * AL * expm1f(v1);
            }
            float h0 = __bfloat162float(__float2bfloat16(z[0]));
            float h1 = __bfloat162float(__float2bfloat16(z[1]));
            float h2 = __bfloat162float(__float2bfloat16(z[2]));
            float h3 = __bfloat162float(__float2bfloat16(z[3]));
            float h4 = __bfloat162float(__float2bfloat16(z[4]));
            float h5 = __bfloat162float(__float2bfloat16(z[5]));
            float h6 = __bfloat162float(__float2bfloat16(z[6]));
            float h7 = __bfloat162float(__float2bfloat16(z[7]));
            a2h[kt2][0] = pack2bf(z[0], z[1]);
            a2h[kt2][1] = pack2bf(z[2], z[3]);
            a2h[kt2][2] = pack2bf(z[4], z[5]);
            a2h[kt2][3] = pack2bf(z[6], z[7]);
            a2l[kt2][0] = pack2bf(z[0] - h0, z[1] - h1);
            a2l[kt2][1] = pack2bf(z[2] - h2, z[3] - h3);
            a2l[kt2][2] = pack2bf(z[4] - h4, z[5] - h5);
            a2l[kt2][3] = pack2bf(z[6] - h6, z[7] - h7);
        }

        // agg_g (X) ready; F_{g+1} (Y) may stay in flight
        CP_WAIT(1);
        __syncthreads();

        // ---- MMA2: D2 += G_g @ agg_g^T (3-term split, acc over g) ----
        #pragma unroll
        for (int kt = 0; kt < 8; kt++) {
            #pragma unroll
            for (int ntp = 0; ntp < 8; ntp++) {
                uint32_t bh[4], bl[4];
                ldsm4(bh, sb + OF3_B_HI + SW_OFF(16 * ntp + b_rowi, 2 * kt + b_chA));
                ldsm4(bl, sb + OF3_B_LO + SW_OFF(16 * ntp + b_rowi, 2 * kt + b_chA));
                mma16816(d2[2 * ntp],     a2h[kt], bh);
                mma16816(d2[2 * ntp],     a2h[kt], bl);
                mma16816(d2[2 * ntp],     a2l[kt], bh);
                mma16816(d2[2 * ntp + 1], a2h[kt], bh + 2);
                mma16816(d2[2 * ntp + 1], a2h[kt], bl + 2);
                mma16816(d2[2 * ntp + 1], a2l[kt], bh + 2);
            }
        }
        __syncthreads();   // all warps done reading B-slot(agg_g)

        // refill B-slot with sfw for next MMA1 (group Z; waited at loop top with Y)
        if (g + 1 < NPOS) {
            stage_async_n(sb + OF3_B_HI, g_sfw_hi, CH, tid, 2048);
            stage_async_n(sb + OF3_B_LO, g_sfw_lo, CH, tid, 2048);
            CP_COMMIT();
        }
    }

    // ---- epilogue: row L2 norm + store ----
    float ssA = 0.f, ssB = 0.f;
    #pragma unroll
    for (int n = 0; n < 16; n++) {
        ssA = fmaf(d2[n][0], d2[n][0], fmaf(d2[n][1], d2[n][1], ssA));
        ssB = fmaf(d2[n][2], d2[n][2], fmaf(d2[n][3], d2[n][3], ssB));
    }
    ssA += __shfl_xor_sync(0xffffffffu, ssA, 1);
    ssA += __shfl_xor_sync(0xffffffffu, ssA, 2);
    ssB += __shfl_xor_sync(0xffffffffu, ssB, 1);
    ssB += __shfl_xor_sync(0xffffffffu, ssB, 2);
    float invA = 1.f / fmaxf(sqrtf(ssA), 1e-12f);
    float invB = 1.f / fmaxf(sqrtf(ssB), 1e-12f);

    int gg = lane >> 2, t = lane & 3;
    float* rowA = out + (size_t)(kp0 + m0w + gg) * CH;
    float* rowB = out + (size_t)(kp0 + m0w + gg + 8) * CH;
    #pragma unroll
    for (int n = 0; n < 16; n++) {
        int col = n * 8 + 2 * t;
        *(float2*)(rowA + col) = make_float2(d2[n][0] * invA, d2[n][1] * invA);
        *(float2*)(rowB + col) = make_float2(d2[n][2] * invB, d2[n][3] * invB);
    }
}

// ---------------- launch ---------------------------------------------------------
extern "C" void kernel_launch(void* const* d_in, const int* in_sizes, int n_in,
                              void* d_out, int out_size) {
    (void)in_sizes; (void)n_in; (void)out_size;
    const float* x    = (const float*)d_in[0];
    const float* kpts = (const float*)d_in[1];
    const float* w1   = (const float*)d_in[2];
    const float* b1   = (const float*)d_in[3];
    const float* w2   = (const float*)d_in[4];
    const float* b2   = (const float*)d_in[5];
    const float* sfw  = (const float*)d_in[6];
    const float* aggw = (const float*)d_in[7];
    float* out = (float*)d_out;

    const int smemOff = 16 * 9 * CH * sizeof(float);   // 73.7 KB
    cudaFuncSetAttribute(k_off,   cudaFuncAttributeMaxDynamicSharedMemorySize, smemOff);
    cudaFuncSetAttribute(k_fused, cudaFuncAttributeMaxDynamicSharedMemorySize, SMEM_FUSED);

    k_transpose<<<dim3(HWSZ / 32, CH / 32, BB), dim3(32, 8)>>>(x);
    k_prep<<<dim3(4, 4, NPOS + 1), dim3(32, 8)>>>(aggw, sfw);
    k_off<<<NKP_TOT / 32, 512, smemOff>>>(kpts, w1, b1, w2, b2);
    k_bil<<<MROWS / 8, 256>>>();
    k_fused<<<NKP_TOT / 64, 128, SMEM_FUSED>>>(out);
}

// round 15
// speedup vs baseline: 1.1486x; 1.0544x over previous
#include <cuda_runtime.h>
#include <cuda_bf16.h>
#include <math.h>
#include <cstdint>

#define BB   4
#define CH   128
#define HH   240
#define WW   320
#define NK   4000
#define NPOS 8
#define KSZ  3
#define HWSZ (HH*WW)
#define MAXOFF 80.0f

#define NKP_TOT (BB*NK)          // 16000
#define MROWS   (NKP_TOT*NPOS)   // 128000

// ---------------- scratch (static device globals; no runtime alloc) ------------
__device__ __align__(16) float g_xT[(size_t)BB*HWSZ*CH];        // NHWC
__device__ __align__(16) float2 g_pos[(size_t)MROWS];           // sample positions (px,py)
__device__ __align__(256) __nv_bfloat16 g_fhi[(size_t)MROWS*CH];
__device__ __align__(256) __nv_bfloat16 g_flo[(size_t)MROWS*CH];
__device__ __align__(256) __nv_bfloat16 g_sfw_hi[CH*CH];        // [d][c]
__device__ __align__(256) __nv_bfloat16 g_sfw_lo[CH*CH];
__device__ __align__(256) __nv_bfloat16 g_agg_hi[NPOS*CH*CH];   // [p][d][c]
__device__ __align__(256) __nv_bfloat16 g_agg_lo[NPOS*CH*CH];

// ================= warp-MMA helpers (HMMA path, works on plain sm_103) ==========
__device__ __forceinline__ uint32_t smem_u32(const void* p) {
    return (uint32_t)__cvta_generic_to_shared(p);
}
__device__ __forceinline__ void ldsm4(uint32_t r[4], uint32_t addr) {
    asm volatile("ldmatrix.sync.aligned.m8n8.x4.shared.b16 {%0,%1,%2,%3}, [%4];"
                 : "=r"(r[0]), "=r"(r[1]), "=r"(r[2]), "=r"(r[3]) : "r"(addr));
}
__device__ __forceinline__ void mma16816(float d[4], const uint32_t a[4], const uint32_t b[2]) {
    asm volatile("mma.sync.aligned.m16n8k16.row.col.f32.bf16.bf16.f32 "
                 "{%0,%1,%2,%3}, {%4,%5,%6,%7}, {%8,%9}, {%0,%1,%2,%3};"
                 : "+f"(d[0]), "+f"(d[1]), "+f"(d[2]), "+f"(d[3])
                 : "r"(a[0]), "r"(a[1]), "r"(a[2]), "r"(a[3]), "r"(b[0]), "r"(b[1]));
}
__device__ __forceinline__ uint32_t pack2bf(float a, float b) {
    __nv_bfloat162 t = __floats2bfloat162_rn(a, b);
    return *(uint32_t*)&t;
}
// 16B-chunk XOR swizzle for a tile with 256B rows (16 chunks/row)
#define SW_OFF(row, chunk) ((uint32_t)(row) * 256u + ((uint32_t)((chunk) ^ ((row) & 7)) << 4))

#define CP_ASYNC16(dst, src) \
    asm volatile("cp.async.cg.shared.global [%0], [%1], 16;" :: "r"(dst), "l"(src))
#define CP_COMMIT() asm volatile("cp.async.commit_group;" ::: "memory")
#define CP_WAIT(n)  asm volatile("cp.async.wait_group %0;" :: "n"(n) : "memory")

// ---------------- K1: NCHW -> NHWC transpose ------------------------------------
__global__ void k_transpose(const float* __restrict__ x) {
    __shared__ float tile[32][33];
    int b  = blockIdx.z;
    int c0 = blockIdx.y * 32;
    int hw0 = blockIdx.x * 32;
    int tx = threadIdx.x, ty = threadIdx.y;     // 32 x 8
    const float* xb = x + (size_t)b * CH * HWSZ;
    #pragma unroll
    for (int i = ty; i < 32; i += 8)
        tile[i][tx] = xb[(size_t)(c0 + i) * HWSZ + hw0 + tx];
    __syncthreads();
    float* ob = g_xT + (size_t)b * HWSZ * CH;
    #pragma unroll
    for (int i = ty; i < 32; i += 8)
        ob[(size_t)(hw0 + i) * CH + c0 + tx] = tile[tx][i];
}

// ---------------- merged prep: agg transpose-split (z<NPOS) + sfw split (z==NPOS)
__global__ void k_prep(const float* __restrict__ agg, const float* __restrict__ sfw) {
    __shared__ float t[32][33];
    int p  = blockIdx.z;
    int tx = threadIdx.x, ty = threadIdx.y;     // 32 x 8
    if (p == NPOS) {
        int c0 = blockIdx.x * 32;
        int d0 = blockIdx.y * 32;
        #pragma unroll
        for (int i = ty; i < 32; i += 8) {
            int idx = (d0 + i) * CH + c0 + tx;
            float v = sfw[idx];
            __nv_bfloat16 h = __float2bfloat16(v);
            g_sfw_hi[idx] = h;
            g_sfw_lo[idx] = __float2bfloat16(v - __bfloat162float(h));
        }
        return;
    }
    int c0 = blockIdx.x * 32;
    int d0 = blockIdx.y * 32;
    const float* src = agg + (size_t)p * CH * CH;
    #pragma unroll
    for (int i = ty; i < 32; i += 8)
        t[i][tx] = src[(size_t)(c0 + i) * CH + d0 + tx];
    __syncthreads();
    #pragma unroll
    for (int i = ty; i < 32; i += 8) {
        float v = t[tx][i];
        __nv_bfloat16 h = __float2bfloat16(v);
        size_t oi = (size_t)p * CH * CH + (size_t)(d0 + i) * CH + c0 + tx;
        g_agg_hi[oi] = h;
        g_agg_lo[oi] = __float2bfloat16(v - __bfloat162float(h));
    }
}

// ---------------- K2a: 2-kp-per-warp offset MLP, 512 thr = 32 kp/block ----------
__global__ __launch_bounds__(512) void k_off(
        const float* __restrict__ kpts,
        const float* __restrict__ w1, const float* __restrict__ b1,
        const float* __restrict__ w2, const float* __restrict__ b2) {
    extern __shared__ float w1s[];            // [16][9][128]
    __shared__ float b1s[16];

    int tid = threadIdx.x;
    for (int idx = tid; idx < 16 * 9 * CH; idx += 512) {
        int k  = idx / (9 * CH);
        int r  = idx - k * 9 * CH;
        int ij = r >> 7;
        int c  = r & 127;
        w1s[idx] = w1[(k * CH + c) * 9 + ij];
    }
    if (tid < 16) b1s[tid] = b1[tid];
    __syncthreads();

    int warp = tid >> 5, lane = tid & 31;
    int kpa = blockIdx.x * 32 + warp * 2;
    int kpb = kpa + 1;

    float kxa = kpts[(size_t)kpa * 2 + 0], kya = kpts[(size_t)kpa * 2 + 1];
    float kxb = kpts[(size_t)kpb * 2 + 0], kyb = kpts[(size_t)kpb * 2 + 1];
    float kwxa = (kxa * 0.5f + 0.5f) * (float)(WW - 1);
    float kwya = (kya * 0.5f + 0.5f) * (float)(HH - 1);
    float kwxb = (kxb * 0.5f + 0.5f) * (float)(WW - 1);
    float kwyb = (kyb * 0.5f + 0.5f) * (float)(HH - 1);
    int cxa = min(max((int)((float)((int)kwxa) - 0.5f), 0), WW - 1 - KSZ);
    int cya = min(max((int)((float)((int)kwya) - 0.5f), 0), HH - 1 - KSZ);
    int cxb = min(max((int)((float)((int)kwxb) - 0.5f), 0), WW - 1 - KSZ);
    int cyb = min(max((int)((float)((int)kwyb) - 0.5f), 0), HH - 1 - KSZ);

    const float* basea = g_xT + (size_t)(kpa / NK) * HWSZ * CH + lane * 4;
    const float* baseb = g_xT + (size_t)(kpb / NK) * HWSZ * CH + lane * 4;

    float4 pa[9], pb[9];
    #pragma unroll
    for (int iy = 0; iy < 3; iy++)
        #pragma unroll
        for (int ix = 0; ix < 3; ix++) {
            pa[iy * 3 + ix] = *(const float4*)(basea + ((size_t)(cya + iy) * WW + (cxa + ix)) * CH);
            pb[iy * 3 + ix] = *(const float4*)(baseb + ((size_t)(cyb + iy) * WW + (cxb + ix)) * CH);
        }

    float acc_a[16], acc_b[16];
    #pragma unroll
    for (int k = 0; k < 16; k++) {
        float a = 0.f, b = 0.f;
        #pragma unroll
        for (int ij = 0; ij < 9; ij++) {
            float4 w = *(const float4*)&w1s[(k * 9 + ij) * CH + lane * 4];
            a = fmaf(pa[ij].x, w.x, a); a = fmaf(pa[ij].y, w.y, a);
            a = fmaf(pa[ij].z, w.z, a); a = fmaf(pa[ij].w, w.w, a);
            b = fmaf(pb[ij].x, w.x, b); b = fmaf(pb[ij].y, w.y, b);
            b = fmaf(pb[ij].z, w.z, b); b = fmaf(pb[ij].w, w.w, b);
        }
        acc_a[k] = a; acc_b[k] = b;
    }
    #pragma unroll
    for (int k = 0; k < 16; k++) {
        #pragma unroll
        for (int off = 16; off; off >>= 1) {
            acc_a[k] += __shfl_xor_sync(0xffffffffu, acc_a[k], off);
            acc_b[k] += __shfl_xor_sync(0xffffffffu, acc_b[k], off);
        }
    }

    int n = lane & 15;
    bool isB = lane >= 16;
    float s = b2[n];
    #pragma unroll
    for (int k = 0; k < 16; k++) {
        float v = (isB ? acc_b[k] : acc_a[k]) + b1s[k];
        s = fmaf(fmaxf(v, 0.f), w2[n * 16 + k], s);
    }
    s = fminf(fmaxf(s, -MAXOFF), MAXOFF);

    float oy = __shfl_sync(0xffffffffu, s, (lane & 7) + 8 + (lane & 16));
    if ((lane & 15) < 8) {
        int kp   = isB ? kpb : kpa;
        float kwx = isB ? kwxb : kwxa;
        float kwy = isB ? kwyb : kwya;
        g_pos[(size_t)kp * NPOS + (lane & 7)] = make_float2(kwx + s, kwy + oy);
    }
}

// ---------------- K2b: warp-per-sample bilinear gather -> feats hi/lo -----------
__global__ __launch_bounds__(256) void k_bil() {
    int s = blockIdx.x * 8 + (threadIdx.x >> 5);
    int lane = threadIdx.x & 31;
    int kp = s >> 3;
    int b  = kp / NK;

    float2 pos = g_pos[s];
    float px = pos.x, py = pos.y;
    float x0f = floorf(px), y0f = floorf(py);
    float wx = px - x0f, wy = py - y0f;
    int ix0 = (int)x0f, iy0 = (int)y0f;
    bool xin0 = (x0f >= 0.f) & (x0f <= (float)(WW - 1));
    bool xin1 = (x0f + 1.f >= 0.f) & (x0f + 1.f <= (float)(WW - 1));
    bool yin0 = (y0f >= 0.f) & (y0f <= (float)(HH - 1));
    bool yin1 = (y0f + 1.f >= 0.f) & (y0f + 1.f <= (float)(HH - 1));
    int cx0 = min(max(ix0, 0), WW - 1),     cx1 = min(max(ix0 + 1, 0), WW - 1);
    int cy0 = min(max(iy0, 0), HH - 1),     cy1 = min(max(iy0 + 1, 0), HH - 1);

    const float* base = g_xT + (size_t)b * HWSZ * CH + lane * 4;
    float4 v00 = make_float4(0, 0, 0, 0), v10 = v00, v01 = v00, v11 = v00;
    if (xin0 & yin0) v00 = *(const float4*)(base + ((size_t)cy0 * WW + cx0) * CH);
    if (xin1 & yin0) v10 = *(const float4*)(base + ((size_t)cy0 * WW + cx1) * CH);
    if (xin0 & yin1) v01 = *(const float4*)(base + ((size_t)cy1 * WW + cx0) * CH);
    if (xin1 & yin1) v11 = *(const float4*)(base + ((size_t)cy1 * WW + cx1) * CH);

    float w00 = (1.f - wx) * (1.f - wy), w10 = wx * (1.f - wy);
    float w01 = (1.f - wx) * wy,         w11 = wx * wy;
    float f0 = v00.x * w00 + v10.x * w10 + v01.x * w01 + v11.x * w11;
    float f1 = v00.y * w00 + v10.y * w10 + v01.y * w01 + v11.y * w11;
    float f2 = v00.z * w00 + v10.z * w10 + v01.z * w01 + v11.z * w11;
    float f3 = v00.w * w00 + v10.w * w10 + v01.w * w01 + v11.w * w11;

    float h0 = __bfloat162float(__float2bfloat16(f0));
    float h1 = __bfloat162float(__float2bfloat16(f1));
    float h2 = __bfloat162float(__float2bfloat16(f2));
    float h3 = __bfloat162float(__float2bfloat16(f3));

    size_t o = (size_t)s * CH + lane * 4;
    *(uint2*)(g_fhi + o) = make_uint2(pack2bf(f0, f1), pack2bf(f2, f3));
    *(uint2*)(g_flo + o) = make_uint2(pack2bf(f0 - h0, f1 - h1), pack2bf(f2 - h2, f3 - h3));
}

// ---------------- fused HMMA GEMM: M=64 tile, N split across warp halves --------
// Block = 256 thr / 8 warps: warp (rw = w&3, nh = w>>2) does rows 16rw..+15,
// cols 64nh..+63. G exchanged through the dead F buffer (bf16 hi/lo).
// SMEM: F/G (hi 16K + lo 16K) + B-slot (hi 32K + lo 32K) = 96KB -> 2 blocks/SM.
#define OF3_F_HI  0
#define OF3_F_LO  (16*1024)
#define OF3_B_HI  (32*1024)
#define OF3_B_LO  (64*1024)
#define SMEM_FUSED (96*1024)

__device__ __forceinline__ void stage_async_n(uint32_t dst_sb, const __nv_bfloat16* src,
                                              int row_stride, int tid, int nchunk) {
    #pragma unroll 4
    for (int it = tid; it < nchunk; it += 256) {
        int row = it >> 4, ch = it & 15;
        CP_ASYNC16(dst_sb + SW_OFF(row, ch),
                   (const void*)(src + (size_t)row * row_stride + ch * 8));
    }
}

__global__ __launch_bounds__(256, 2) void k_fused(float* __restrict__ out) {
    extern __shared__ __align__(16) char smem[];
    int tid = threadIdx.x;
    int wid = tid >> 5, lane = tid & 31;
    int rw = wid & 3, nh = wid >> 2;
    int kp0 = blockIdx.x * 64;
    int m0w = rw * 16;

    uint32_t sb = smem_u32(smem);

    // prologue: F_0 (group), sfw -> B-slot (group)
    stage_async_n(sb + OF3_F_HI, g_fhi + ((size_t)kp0 * NPOS + 0) * CH, NPOS * CH, tid, 1024);
    stage_async_n(sb + OF3_F_LO, g_flo + ((size_t)kp0 * NPOS + 0) * CH, NPOS * CH, tid, 1024);
    CP_COMMIT();
    stage_async_n(sb + OF3_B_HI, g_sfw_hi, CH, tid, 2048);
    stage_async_n(sb + OF3_B_LO, g_sfw_lo, CH, tid, 2048);
    CP_COMMIT();

    int a_row = m0w + (lane & 15);
    int a_chA = (lane >> 4);
    int b_rowi = (lane & 7) + ((lane >> 4) << 3);
    int b_chA = (lane >> 3) & 1;
    int b_base = 64 * nh;               // this warp's N-half in B tiles

    float d2[8][4];
    #pragma unroll
    for (int n = 0; n < 8; n++)
        #pragma unroll
        for (int j = 0; j < 4; j++) d2[n][j] = 0.f;

    for (int g = 0; g < NPOS; g++) {
        // F_g and current B-slot contents must be complete
        CP_WAIT(0);
        __syncthreads();

        // ---- MMA1: D1 = feats_g @ sfw^T, this warp's N-half (3-term split) ----
        float d1[8][4];
        #pragma unroll
        for (int n = 0; n < 8; n++)
            #pragma unroll
            for (int j = 0; j < 4; j++) d1[n][j] = 0.f;

        #pragma unroll
        for (int kt = 0; kt < 8; kt++) {
            uint32_t ah[4], al[4];
            ldsm4(ah, sb + OF3_F_HI + SW_OFF(a_row, 2 * kt + a_chA));
            ldsm4(al, sb + OF3_F_LO + SW_OFF(a_row, 2 * kt + a_chA));
            #pragma unroll
            for (int ntp = 0; ntp < 4; ntp++) {
                uint32_t bh[4], bl[4];
                int brow = b_base + 16 * ntp + b_rowi;
                ldsm4(bh, sb + OF3_B_HI + SW_OFF(brow, 2 * kt + b_chA));
                ldsm4(bl, sb + OF3_B_LO + SW_OFF(brow, 2 * kt + b_chA));
                mma16816(d1[2 * ntp],     ah, bh);
                mma16816(d1[2 * ntp],     ah, bl);
                mma16816(d1[2 * ntp],     al, bh);
                mma16816(d1[2 * ntp + 1], ah, bh + 2);
                mma16816(d1[2 * ntp + 1], ah, bl + 2);
                mma16816(d1[2 * ntp + 1], al, bh + 2);
            }
        }
        __syncthreads();   // all warps done with F_g and B-slot(sfw)

        // stream agg_g into B-slot (overlaps SELU + G store)
        stage_async_n(sb + OF3_B_HI, g_agg_hi + (size_t)g * CH * CH, CH, tid, 2048);
        stage_async_n(sb + OF3_B_LO, g_agg_lo + (size_t)g * CH * CH, CH, tid, 2048);
        CP_COMMIT();

        // ---- SELU -> bf16 hi/lo -> STS into F buffer (now the G tile) ----
        const float SC = 1.0507009873554805f, AL = 1.6732632423543772f;
        {
            int r0 = m0w + (lane >> 2);
            uint32_t off4 = (uint32_t)(lane & 3) * 4u;
            #pragma unroll
            for (int n = 0; n < 8; n++) {
                float z0 = d1[n][0], z1 = d1[n][1], z2 = d1[n][2], z3 = d1[n][3];
                z0 = (z0 > 0.f) ? SC * z0 : SC * AL * expm1f(z0);
                z1 = (z1 > 0.f) ? SC * z1 : SC * AL * expm1f(z1);
                z2 = (z2 > 0.f) ? SC * z2 : SC * AL * expm1f(z2);
                z3 = (z3 > 0.f) ? SC * z3 : SC * AL * expm1f(z3);
                float h0 = __bfloat162float(__float2bfloat16(z0));
                float h1 = __bfloat162float(__float2bfloat16(z1));
                float h2 = __bfloat162float(__float2bfloat16(z2));
                float h3 = __bfloat162float(__float2bfloat16(z3));
                int chunk = 8 * nh + n;
                *(uint32_t*)(smem + OF3_F_HI + SW_OFF(r0,     chunk) + off4) = pack2bf(z0, z1);
                *(uint32_t*)(smem + OF3_F_LO + SW_OFF(r0,     chunk) + off4) = pack2bf(z0 - h0, z1 - h1);
                *(uint32_t*)(smem + OF3_F_HI + SW_OFF(r0 + 8, chunk) + off4) = pack2bf(z2, z3);
                *(uint32_t*)(smem + OF3_F_LO + SW_OFF(r0 + 8, chunk) + off4) = pack2bf(z2 - h2, z3 - h3);
            }
        }
        CP_WAIT(0);        // agg_g landed
        __syncthreads();   // G tile complete from all warps + agg visible

        // ---- MMA2: D2 += G @ agg_g^T, this warp's N-half ----
        #pragma unroll
        for (int kt = 0; kt < 8; kt++) {
            uint32_t ah[4], al[4];
            ldsm4(ah, sb + OF3_F_HI + SW_OFF(a_row, 2 * kt + a_chA));
            ldsm4(al, sb + OF3_F_LO + SW_OFF(a_row, 2 * kt + a_chA));
            #pragma unroll
            for (int ntp = 0; ntp < 4; ntp++) {
                uint32_t bh[4], bl[4];
                int brow = b_base + 16 * ntp + b_rowi;
                ldsm4(bh, sb + OF3_B_HI + SW_OFF(brow, 2 * kt + b_chA));
                ldsm4(bl, sb + OF3_B_LO + SW_OFF(brow, 2 * kt + b_chA));
                mma16816(d2[2 * ntp],     ah, bh);
                mma16816(d2[2 * ntp],     ah, bl);
                mma16816(d2[2 * ntp],     al, bh);
                mma16816(d2[2 * ntp + 1], ah, bh + 2);
                mma16816(d2[2 * ntp + 1], ah, bl + 2);
                mma16816(d2[2 * ntp + 1], al, bh + 2);
            }
        }
        __syncthreads();   // all warps done with G tile and B-slot(agg)

        // prefetch F_{g+1} and refill sfw (overlap with other co-resident block)
        if (g + 1 < NPOS) {
            stage_async_n(sb + OF3_F_HI, g_fhi + ((size_t)kp0 * NPOS + g + 1) * CH, NPOS * CH, tid, 1024);
            stage_async_n(sb + OF3_F_LO, g_flo + ((size_t)kp0 * NPOS + g + 1) * CH, NPOS * CH, tid, 1024);
            stage_async_n(sb + OF3_B_HI, g_sfw_hi, CH, tid, 2048);
            stage_async_n(sb + OF3_B_LO, g_sfw_lo, CH, tid, 2048);
            CP_COMMIT();
        }
    }

    // ---- epilogue: cross-half row L2 norm + store ----
    float* nrm = (float*)(smem + OF3_B_HI);   // [64][2] partial sums (synced above)
    {
        float ssA = 0.f, ssB = 0.f;
        #pragma unroll
        for (int n = 0; n < 8; n++) {
            ssA = fmaf(d2[n][0], d2[n][0], fmaf(d2[n][1], d2[n][1], ssA));
            ssB = fmaf(d2[n][2], d2[n][2], fmaf(d2[n][3], d2[n][3], ssB));
        }
        ssA += __shfl_xor_sync(0xffffffffu, ssA, 1);
        ssA += __shfl_xor_sync(0xffffffffu, ssA, 2);
        ssB += __shfl_xor_sync(0xffffffffu, ssB, 1);
        ssB += __shfl_xor_sync(0xffffffffu, ssB, 2);
        int r0 = m0w + (lane >> 2);
        if ((lane & 3) == 0) {
            nrm[r0 * 2 + nh]       = ssA;
            nrm[(r0 + 8) * 2 + nh] = ssB;
        }
    }
    __syncthreads();

    {
        int r0 = m0w + (lane >> 2);
        float invA = 1.f / fmaxf(sqrtf(nrm[r0 * 2] + nrm[r0 * 2 + 1]), 1e-12f);
        float invB = 1.f / fmaxf(sqrtf(nrm[(r0 + 8) * 2] + nrm[(r0 + 8) * 2 + 1]), 1e-12f);
        int t = lane & 3;
        float* rowA = out + (size_t)(kp0 + r0) * CH + 64 * nh;
        float* rowB = out + (size_t)(kp0 + r0 + 8) * CH + 64 * nh;
        #pragma unroll
        for (int n = 0; n < 8; n++) {
            int col = n * 8 + 2 * t;
            *(float2*)(rowA + col) = make_float2(d2[n][0] * invA, d2[n][1] * invA);
            *(float2*)(rowB + col) = make_float2(d2[n][2] * invB, d2[n][3] * invB);
        }
    }
}

// ---------------- launch ---------------------------------------------------------
extern "C" void kernel_launch(void* const* d_in, const int* in_sizes, int n_in,
                              void* d_out, int out_size) {
    (void)in_sizes; (void)n_in; (void)out_size;
    const float* x    = (const float*)d_in[0];
    const float* kpts = (const float*)d_in[1];
    const float* w1   = (const float*)d_in[2];
    const float* b1   = (const float*)d_in[3];
    const float* w2   = (const float*)d_in[4];
    const float* b2   = (const float*)d_in[5];
    const float* sfw  = (const float*)d_in[6];
    const float* aggw = (const float*)d_in[7];
    float* out = (float*)d_out;

    const int smemOff = 16 * 9 * CH * sizeof(float);   // 73.7 KB
    cudaFuncSetAttribute(k_off,   cudaFuncAttributeMaxDynamicSharedMemorySize, smemOff);
    cudaFuncSetAttribute(k_fused, cudaFuncAttributeMaxDynamicSharedMemorySize, SMEM_FUSED);

    k_transpose<<<dim3(HWSZ / 32, CH / 32, BB), dim3(32, 8)>>>(x);
    k_prep<<<dim3(4, 4, NPOS + 1), dim3(32, 8)>>>(aggw, sfw);
    k_off<<<NKP_TOT / 32, 512, smemOff>>>(kpts, w1, b1, w2, b2);
    k_bil<<<MROWS / 8, 256>>>();
    k_fused<<<NKP_TOT / 64, 256, SMEM_FUSED>>>(out);
}